// round 3
// baseline (speedup 1.0000x reference)
#include <cuda_runtime.h>
#include <cuda_bf16.h>
#include <math.h>

// Problem constants
#define L_SEQ 2048
#define E_DIM 512
#define H2    512
#define G4    2048            // 4*H2 gate rows per direction
#define NT    12
#define START 10
#define STOP  11
#define NEGV  -10000.0f

#define NCTA_DIR 64           // CTAs per direction
#define RPC 8                 // hidden units per CTA
#define GROWS 32              // gate rows per CTA

// ---------------- device scratch (no cudaMalloc allowed) ----------------
__device__ float g_xs[L_SEQ * E_DIM];              // embedded sentence, 4 MB
__device__ float g_xw[2 * L_SEQ * G4];             // precomputed input projections (permuted)
__device__ float g_hs[2][(L_SEQ + 1) * H2];        // h history per direction (slot 0 = h0)
__device__ float g_feats[L_SEQ * NT];
__device__ float g_chunk[128][NT * NT];            // CRF chunk matrices
__device__ unsigned g_flag[2][NCTA_DIR];           // per-CTA step-completion flags

// ---------------- init: embedding gather + flags/h0 init ----------------
__global__ void init_kernel(const int* __restrict__ sentence,
                            const float* __restrict__ emb,
                            const float* __restrict__ h0)
{
    int b = blockIdx.x;
    if (b < L_SEQ) {
        int row = sentence[b];
        const float4* src = (const float4*)(emb + (size_t)row * E_DIM);
        float4* dst = (float4*)(g_xs + (size_t)b * E_DIM);
        dst[threadIdx.x] = src[threadIdx.x];   // 128 threads x float4 = 512 floats
    } else {
        if (threadIdx.x < 2 * NCTA_DIR) ((unsigned*)g_flag)[threadIdx.x] = 0;
        const float4* s = (const float4*)h0;
        for (int i = threadIdx.x; i < 2 * (H2 / 4); i += 128) {
            int d = i >> 7;
            int q = i & 127;
            ((float4*)(g_hs[d]))[q] = s[i];
        }
    }
}

// ---------------- input projection GEMM: xw = xs @ Wih^T + b ----------------
// Output permuted so scan-CTA `sub` reads 32 contiguous floats:
//   gate row n (= g*512 + j) -> xw[dir][pos][ (j>>3)*32 + g*8 + (j&7) ]
#define BM 128
#define BN 64
#define BK 16
__global__ void __launch_bounds__(256) xproj_kernel(
    const float* __restrict__ Wf, const float* __restrict__ Wb,
    const float* __restrict__ bfv, const float* __restrict__ bbv)
{
    __shared__ float As[BK][BM + 4];
    __shared__ float Bs[BK][BN + 4];
    const int dir = blockIdx.z;
    const float* W    = dir ? Wb  : Wf;
    const float* bias = dir ? bbv : bfv;
    const int m0 = blockIdx.x * BM;
    const int n0 = blockIdx.y * BN;
    const int tid = threadIdx.x;
    const int tx = tid & 15, ty = tid >> 4;

    float acc[8][4] = {};
    for (int k0 = 0; k0 < E_DIM; k0 += BK) {
        #pragma unroll
        for (int u = 0; u < 2; ++u) {
            int idx = tid + u * 256;
            int r = idx >> 2, q = idx & 3;
            float4 v = *(const float4*)(g_xs + (size_t)(m0 + r) * E_DIM + k0 + q * 4);
            As[q*4+0][r] = v.x; As[q*4+1][r] = v.y; As[q*4+2][r] = v.z; As[q*4+3][r] = v.w;
        }
        {
            int r = tid >> 2, q = tid & 3;
            float4 v = *(const float4*)(W + (size_t)(n0 + r) * E_DIM + k0 + q * 4);
            Bs[q*4+0][r] = v.x; Bs[q*4+1][r] = v.y; Bs[q*4+2][r] = v.z; Bs[q*4+3][r] = v.w;
        }
        __syncthreads();
        #pragma unroll
        for (int kk = 0; kk < BK; ++kk) {
            float a[8], b[4];
            #pragma unroll
            for (int i = 0; i < 8; ++i) a[i] = As[kk][ty * 8 + i];
            #pragma unroll
            for (int j = 0; j < 4; ++j) b[j] = Bs[kk][tx * 4 + j];
            #pragma unroll
            for (int i = 0; i < 8; ++i)
                #pragma unroll
                for (int j = 0; j < 4; ++j) acc[i][j] += a[i] * b[j];
        }
        __syncthreads();
    }
    // epilogue: add bias, permuted store (4 output cols stay contiguous)
    const int nb = n0 + tx * 4;          // 4-aligned gate row
    const int g  = nb >> 9, jj = nb & 511;
    const int sub = jj >> 3, slot = g * 8 + (jj & 7);   // slot 4-aligned
    float b0 = bias[nb], b1 = bias[nb+1], b2 = bias[nb+2], b3 = bias[nb+3];
    #pragma unroll
    for (int i = 0; i < 8; ++i) {
        int m = m0 + ty * 8 + i;
        float4 o;
        o.x = acc[i][0] + b0; o.y = acc[i][1] + b1;
        o.z = acc[i][2] + b2; o.w = acc[i][3] + b3;
        *(float4*)(g_xw + ((size_t)(dir * L_SEQ + m)) * G4 + sub * 32 + slot) = o;
    }
}

// ---------------- persistent bidirectional LSTM scan (Whh only) ----------------
__global__ void __launch_bounds__(256, 1) lstm_kernel(
    const float* __restrict__ Whhf, const float* __restrict__ Whhb,
    const float* __restrict__ c0)
{
    extern __shared__ float sm[];
    float* Whh_s = sm;                 // 32*512 = 16384 floats (64 KB)
    float* gsum  = sm + GROWS * H2;    // 32
    float* c_s   = gsum + GROWS;       // 8

    const int dir = blockIdx.x / NCTA_DIR;
    const int sub = blockIdx.x % NCTA_DIR;
    const int k0  = sub * RPC;
    const float* Whh = dir ? Whhb : Whhf;
    const int tid = threadIdx.x;

    // load this CTA's 32 Whh gate rows into SMEM
    for (int i = tid; i < GROWS * (H2 / 4); i += 256) {
        int lr = i >> 7, c4 = i & 127;
        int g = lr >> 3, k = lr & 7;
        ((float4*)Whh_s)[i] = ((const float4*)(Whh + (size_t)(g * H2 + k0 + k) * H2))[c4];
    }
    if (tid < RPC) c_s[tid] = c0[dir * H2 + k0 + tid];
    __syncthreads();

    float* hist = g_hs[dir];
    const float* xw_base = g_xw + (size_t)dir * L_SEQ * G4 + sub * 32;
    unsigned* flags = g_flag[dir];
    const int w = tid >> 5, l = tid & 31;

    for (int t = 0; t < L_SEQ; ++t) {
        const int pos = dir ? (L_SEQ - 1 - t) : t;

        // prefetch this warp's 4 xw values (lane 0) — recurrence-independent
        float xr[4];
        if (l == 0) {
            const float* xp = xw_base + (size_t)pos * G4;
            #pragma unroll
            for (int r = 0; r < 4; ++r) xr[r] = __ldcg(xp + w * 4 + r);
        }

        // wait for all 64 producer flags of this direction to reach t (wrap-proof compare)
        if (tid < NCTA_DIR) {
            unsigned v;
            do {
                asm volatile("ld.acquire.gpu.u32 %0, [%1];" : "=r"(v) : "l"(flags + tid));
            } while ((int)(v - (unsigned)t) < 0);
        }
        __syncthreads();

        // load h_t directly to registers (ordered by the acquire + barrier)
        const float4* hv = (const float4*)(hist + (size_t)t * H2);
        float4 h4[4];
        #pragma unroll
        for (int j = 0; j < 4; ++j) h4[j] = __ldcg(hv + l + 32 * j);

        // GEMV: warp w computes gate rows 4w..4w+3
        #pragma unroll
        for (int r = 0; r < 4; ++r) {
            const int lr = w * 4 + r;
            const float4* wr = (const float4*)(Whh_s + lr * H2);
            float acc = 0.f;
            #pragma unroll
            for (int j = 0; j < 4; ++j) {
                float4 ww = wr[l + 32 * j];
                acc += ww.x * h4[j].x + ww.y * h4[j].y + ww.z * h4[j].z + ww.w * h4[j].w;
            }
            #pragma unroll
            for (int off = 16; off; off >>= 1) acc += __shfl_xor_sync(0xffffffffu, acc, off);
            if (l == 0) gsum[lr] = acc + xr[r];
        }
        __syncthreads();

        // gate update + publish (warp 0 only; other warps race ahead to next poll)
        if (tid < 32) {
            if (tid < RPC) {
                float ig = 1.f / (1.f + expf(-gsum[tid]));
                float fg = 1.f / (1.f + expf(-gsum[8 + tid]));
                float gg = tanhf(gsum[16 + tid]);
                float og = 1.f / (1.f + expf(-gsum[24 + tid]));
                float c = fg * c_s[tid] + ig * gg;
                c_s[tid] = c;
                float hn = og * tanhf(c);
                __stcg(hist + (size_t)(t + 1) * H2 + k0 + tid, hn);
            }
            __syncwarp();
            if (tid == 0)
                asm volatile("st.release.gpu.u32 [%0], %1;"
                             :: "l"(flags + sub), "r"((unsigned)(t + 1)) : "memory");
        }
    }
}

// ---------------- output projection: feats[t][i] ----------------
__global__ void feats_kernel(const float* __restrict__ W_out, const float* __restrict__ b_out)
{
    int t = blockIdx.x;
    int w = threadIdx.x >> 5, l = threadIdx.x & 31;  // 12 warps
    const float* hf = g_hs[0] + (size_t)(t + 1) * H2;
    const float* hb = g_hs[1] + (size_t)(L_SEQ - t) * H2;
    const float* wo = W_out + (size_t)w * (2 * H2);
    float acc = 0.f;
    for (int c = l; c < H2; c += 32)
        acc += hf[c] * wo[c] + hb[c] * wo[H2 + c];
    #pragma unroll
    for (int off = 16; off; off >>= 1) acc += __shfl_xor_sync(0xffffffffu, acc, off);
    if (l == 0) g_feats[t * NT + w] = acc + b_out[w];
}

// ---------------- CRF: chunked log-semiring scan ----------------
__global__ void crf_chunk_kernel(const float* __restrict__ trans)
{
    __shared__ float tr[NT * NT], cur[NT * NT];
    int tid = threadIdx.x;           // 0..143
    int i = tid / NT, j = tid % NT;
    tr[tid] = trans[tid];
    int t0 = blockIdx.x * 16;
    cur[tid] = trans[tid] + g_feats[t0 * NT + i];
    __syncthreads();
    for (int s = 1; s < 16; ++s) {
        float ft = g_feats[(t0 + s) * NT + i];
        float v[NT];
        float m = -3.4e38f;
        #pragma unroll
        for (int k = 0; k < NT; ++k) { v[k] = tr[i * NT + k] + cur[k * NT + j]; m = fmaxf(m, v[k]); }
        float ssum = 0.f;
        #pragma unroll
        for (int k = 0; k < NT; ++k) ssum += expf(v[k] - m);
        float r = ft + m + logf(ssum);
        __syncthreads();
        cur[tid] = r;
        __syncthreads();
    }
    g_chunk[blockIdx.x][tid] = cur[tid];
}

__global__ void crf_final_kernel(const float* __restrict__ trans, float* __restrict__ out)
{
    __shared__ float fv[NT], nfv[NT];
    int tid = threadIdx.x;
    if (tid < NT) fv[tid] = (tid == START) ? 0.f : NEGV;
    __syncwarp();
    for (int b = 0; b < 128; ++b) {
        if (tid < NT) {
            float m = -3.4e38f, v[NT];
            #pragma unroll
            for (int k = 0; k < NT; ++k) { v[k] = g_chunk[b][tid * NT + k] + fv[k]; m = fmaxf(m, v[k]); }
            float s = 0.f;
            #pragma unroll
            for (int k = 0; k < NT; ++k) s += expf(v[k] - m);
            nfv[tid] = m + logf(s);
        }
        __syncwarp();
        if (tid < NT) fv[tid] = nfv[tid];
        __syncwarp();
    }
    if (tid == 0) {
        float m = -3.4e38f, v[NT];
        #pragma unroll
        for (int k = 0; k < NT; ++k) { v[k] = trans[STOP * NT + k] + fv[k]; m = fmaxf(m, v[k]); }
        float s = 0.f;
        #pragma unroll
        for (int k = 0; k < NT; ++k) s += expf(v[k] - m);
        out[0] = m + logf(s);
    }
}

// ---------------- launch ----------------
extern "C" void kernel_launch(void* const* d_in, const int* in_sizes, int n_in,
                              void* d_out, int out_size)
{
    const int*   sentence = (const int*)  d_in[0];
    const float* emb      = (const float*)d_in[1];
    const float* Wihf     = (const float*)d_in[2];
    const float* Whhf     = (const float*)d_in[3];
    const float* bf       = (const float*)d_in[4];
    const float* Wihb     = (const float*)d_in[5];
    const float* Whhb     = (const float*)d_in[6];
    const float* bb       = (const float*)d_in[7];
    const float* Wout     = (const float*)d_in[8];
    const float* bout     = (const float*)d_in[9];
    const float* trans    = (const float*)d_in[10];
    const float* h0       = (const float*)d_in[11];
    const float* c0       = (const float*)d_in[12];

    const size_t smem_bytes = (size_t)(GROWS * H2 + GROWS + RPC) * sizeof(float);
    cudaFuncSetAttribute(lstm_kernel, cudaFuncAttributeMaxDynamicSharedMemorySize, (int)smem_bytes);

    init_kernel<<<L_SEQ + 1, 128>>>(sentence, emb, h0);
    xproj_kernel<<<dim3(L_SEQ / BM, G4 / BN, 2), 256>>>(Wihf, Wihb, bf, bb);
    lstm_kernel<<<2 * NCTA_DIR, 256, smem_bytes>>>(Whhf, Whhb, c0);
    feats_kernel<<<L_SEQ, 384>>>(Wout, bout);
    crf_chunk_kernel<<<128, NT * NT>>>(trans);
    crf_final_kernel<<<1, 32>>>(trans, (float*)d_out);
}

// round 4
// speedup vs baseline: 1.3237x; 1.3237x over previous
#include <cuda_runtime.h>
#include <cuda_bf16.h>
#include <math.h>

// Problem constants
#define L_SEQ 2048
#define E_DIM 512
#define H2    512
#define G4    2048            // 4*H2 gate rows per direction
#define NT    12
#define START 10
#define STOP  11
#define NEGV  -10000.0f

#define NCTA_DIR 64           // CTAs per direction
#define RPC 8                 // hidden units per CTA
#define GROWS 32              // gate rows per CTA

// ---------------- device scratch (no cudaMalloc allowed) ----------------
__device__ float g_xs[L_SEQ * E_DIM];              // embedded sentence, 4 MB
__device__ float g_xw[2 * L_SEQ * G4];             // precomputed input projections (permuted)
__device__ float g_hs[2][(L_SEQ + 1) * H2];        // h history per direction (slot 0 = h0)
__device__ float g_feats[L_SEQ * NT];
__device__ float g_chunk[128][NT * NT];            // CRF chunk matrices
__device__ unsigned g_flag[2][NCTA_DIR];           // per-CTA step-completion flags

// ---------------- init: embedding gather + flags/h0 init ----------------
__global__ void init_kernel(const int* __restrict__ sentence,
                            const float* __restrict__ emb,
                            const float* __restrict__ h0)
{
    int b = blockIdx.x;
    if (b < L_SEQ) {
        int row = sentence[b];
        const float4* src = (const float4*)(emb + (size_t)row * E_DIM);
        float4* dst = (float4*)(g_xs + (size_t)b * E_DIM);
        dst[threadIdx.x] = src[threadIdx.x];   // 128 threads x float4 = 512 floats
    } else {
        if (threadIdx.x < 2 * NCTA_DIR) ((unsigned*)g_flag)[threadIdx.x] = 0;
        const float4* s = (const float4*)h0;
        for (int i = threadIdx.x; i < 2 * (H2 / 4); i += 128) {
            int d = i >> 7;
            int q = i & 127;
            ((float4*)(g_hs[d]))[q] = s[i];
        }
    }
}

// ---------------- input projection GEMM: xw = xs @ Wih^T + b ----------------
// Output permuted so scan-CTA `sub` reads 32 contiguous floats:
//   gate row n (= g*512 + j) -> xw[dir][pos][ (j>>3)*32 + g*8 + (j&7) ]
#define BM 128
#define BN 64
#define BK 16
__global__ void __launch_bounds__(256) xproj_kernel(
    const float* __restrict__ Wf, const float* __restrict__ Wb,
    const float* __restrict__ bfv, const float* __restrict__ bbv)
{
    __shared__ float As[BK][BM + 4];
    __shared__ float Bs[BK][BN + 4];
    const int dir = blockIdx.z;
    const float* W    = dir ? Wb  : Wf;
    const float* bias = dir ? bbv : bfv;
    const int m0 = blockIdx.x * BM;
    const int n0 = blockIdx.y * BN;
    const int tid = threadIdx.x;
    const int tx = tid & 15, ty = tid >> 4;

    float acc[8][4] = {};
    for (int k0 = 0; k0 < E_DIM; k0 += BK) {
        #pragma unroll
        for (int u = 0; u < 2; ++u) {
            int idx = tid + u * 256;
            int r = idx >> 2, q = idx & 3;
            float4 v = *(const float4*)(g_xs + (size_t)(m0 + r) * E_DIM + k0 + q * 4);
            As[q*4+0][r] = v.x; As[q*4+1][r] = v.y; As[q*4+2][r] = v.z; As[q*4+3][r] = v.w;
        }
        {
            int r = tid >> 2, q = tid & 3;
            float4 v = *(const float4*)(W + (size_t)(n0 + r) * E_DIM + k0 + q * 4);
            Bs[q*4+0][r] = v.x; Bs[q*4+1][r] = v.y; Bs[q*4+2][r] = v.z; Bs[q*4+3][r] = v.w;
        }
        __syncthreads();
        #pragma unroll
        for (int kk = 0; kk < BK; ++kk) {
            float a[8], b[4];
            #pragma unroll
            for (int i = 0; i < 8; ++i) a[i] = As[kk][ty * 8 + i];
            #pragma unroll
            for (int j = 0; j < 4; ++j) b[j] = Bs[kk][tx * 4 + j];
            #pragma unroll
            for (int i = 0; i < 8; ++i)
                #pragma unroll
                for (int j = 0; j < 4; ++j) acc[i][j] += a[i] * b[j];
        }
        __syncthreads();
    }
    // epilogue: add bias, permuted store (4 output cols stay contiguous)
    const int nb = n0 + tx * 4;          // 4-aligned gate row
    const int g  = nb >> 9, jj = nb & 511;
    const int sub = jj >> 3, slot = g * 8 + (jj & 7);   // slot 4-aligned
    float b0 = bias[nb], b1 = bias[nb+1], b2 = bias[nb+2], b3 = bias[nb+3];
    #pragma unroll
    for (int i = 0; i < 8; ++i) {
        int m = m0 + ty * 8 + i;
        float4 o;
        o.x = acc[i][0] + b0; o.y = acc[i][1] + b1;
        o.z = acc[i][2] + b2; o.w = acc[i][3] + b3;
        *(float4*)(g_xw + ((size_t)(dir * L_SEQ + m)) * G4 + sub * 32 + slot) = o;
    }
}

// ---------------- persistent bidirectional LSTM scan (Whh only) ----------------
__global__ void __launch_bounds__(256, 1) lstm_kernel(
    const float* __restrict__ Whhf, const float* __restrict__ Whhb,
    const float* __restrict__ c0)
{
    extern __shared__ float sm[];
    float* Whh_s = sm;                 // 32*512 = 16384 floats (64 KB)
    float* gsum  = sm + GROWS * H2;    // 32
    float* c_s   = gsum + GROWS;       // 8

    const int dir = blockIdx.x / NCTA_DIR;
    const int sub = blockIdx.x % NCTA_DIR;
    const int k0  = sub * RPC;
    const float* Whh = dir ? Whhb : Whhf;
    const int tid = threadIdx.x;

    // load this CTA's 32 Whh gate rows into SMEM
    for (int i = tid; i < GROWS * (H2 / 4); i += 256) {
        int lr = i >> 7, c4 = i & 127;
        int g = lr >> 3, k = lr & 7;
        ((float4*)Whh_s)[i] = ((const float4*)(Whh + (size_t)(g * H2 + k0 + k) * H2))[c4];
    }
    if (tid < RPC) c_s[tid] = c0[dir * H2 + k0 + tid];
    __syncthreads();

    float* hist = g_hs[dir];
    const float* xw_base = g_xw + (size_t)dir * L_SEQ * G4 + sub * 32;
    unsigned* flags = g_flag[dir];
    const int w = tid >> 5, l = tid & 31;

    for (int t = 0; t < L_SEQ; ++t) {
        const int pos = dir ? (L_SEQ - 1 - t) : t;

        // prefetch this warp's 4 xw values (lane 0) — recurrence-independent
        float xr[4];
        if (l == 0) {
            const float* xp = xw_base + (size_t)pos * G4;
            #pragma unroll
            for (int r = 0; r < 4; ++r) xr[r] = __ldcg(xp + w * 4 + r);
        }

        // wait for all 64 producer flags of this direction to reach t (wrap-proof compare)
        if (tid < NCTA_DIR) {
            unsigned v;
            do {
                asm volatile("ld.acquire.gpu.u32 %0, [%1];" : "=r"(v) : "l"(flags + tid));
            } while ((int)(v - (unsigned)t) < 0);
        }
        __syncthreads();

        // load h_t directly to registers (ordered by the acquire + barrier)
        const float4* hv = (const float4*)(hist + (size_t)t * H2);
        float4 h4[4];
        #pragma unroll
        for (int j = 0; j < 4; ++j) h4[j] = __ldcg(hv + l + 32 * j);

        // GEMV: warp w computes gate rows 4w..4w+3
        #pragma unroll
        for (int r = 0; r < 4; ++r) {
            const int lr = w * 4 + r;
            const float4* wr = (const float4*)(Whh_s + lr * H2);
            float acc = 0.f;
            #pragma unroll
            for (int j = 0; j < 4; ++j) {
                float4 ww = wr[l + 32 * j];
                acc += ww.x * h4[j].x + ww.y * h4[j].y + ww.z * h4[j].z + ww.w * h4[j].w;
            }
            #pragma unroll
            for (int off = 16; off; off >>= 1) acc += __shfl_xor_sync(0xffffffffu, acc, off);
            if (l == 0) gsum[lr] = acc + xr[r];
        }
        __syncthreads();

        // gate update + publish (warp 0 only; other warps race ahead to next poll)
        if (tid < 32) {
            if (tid < RPC) {
                float ig = 1.f / (1.f + expf(-gsum[tid]));
                float fg = 1.f / (1.f + expf(-gsum[8 + tid]));
                float gg = tanhf(gsum[16 + tid]);
                float og = 1.f / (1.f + expf(-gsum[24 + tid]));
                float c = fg * c_s[tid] + ig * gg;
                c_s[tid] = c;
                float hn = og * tanhf(c);
                __stcg(hist + (size_t)(t + 1) * H2 + k0 + tid, hn);
            }
            __syncwarp();
            if (tid == 0)
                asm volatile("st.release.gpu.u32 [%0], %1;"
                             :: "l"(flags + sub), "r"((unsigned)(t + 1)) : "memory");
        }
    }
}

// ---------------- output projection: feats[t][i] ----------------
__global__ void feats_kernel(const float* __restrict__ W_out, const float* __restrict__ b_out)
{
    int t = blockIdx.x;
    int w = threadIdx.x >> 5, l = threadIdx.x & 31;  // 12 warps
    const float* hf = g_hs[0] + (size_t)(t + 1) * H2;
    const float* hb = g_hs[1] + (size_t)(L_SEQ - t) * H2;
    const float* wo = W_out + (size_t)w * (2 * H2);
    float acc = 0.f;
    for (int c = l; c < H2; c += 32)
        acc += hf[c] * wo[c] + hb[c] * wo[H2 + c];
    #pragma unroll
    for (int off = 16; off; off >>= 1) acc += __shfl_xor_sync(0xffffffffu, acc, off);
    if (l == 0) g_feats[t * NT + w] = acc + b_out[w];
}

// ---------------- CRF: chunked log-semiring scan ----------------
__global__ void crf_chunk_kernel(const float* __restrict__ trans)
{
    __shared__ float tr[NT * NT], cur[NT * NT];
    int tid = threadIdx.x;           // 0..143
    int i = tid / NT, j = tid % NT;
    tr[tid] = trans[tid];
    int t0 = blockIdx.x * 16;
    cur[tid] = trans[tid] + g_feats[t0 * NT + i];
    __syncthreads();
    for (int s = 1; s < 16; ++s) {
        float ft = g_feats[(t0 + s) * NT + i];
        float v[NT];
        float m = -3.4e38f;
        #pragma unroll
        for (int k = 0; k < NT; ++k) { v[k] = tr[i * NT + k] + cur[k * NT + j]; m = fmaxf(m, v[k]); }
        float ssum = 0.f;
        #pragma unroll
        for (int k = 0; k < NT; ++k) ssum += expf(v[k] - m);
        float r = ft + m + logf(ssum);
        __syncthreads();
        cur[tid] = r;
        __syncthreads();
    }
    g_chunk[blockIdx.x][tid] = cur[tid];
}

__global__ void crf_final_kernel(const float* __restrict__ trans, float* __restrict__ out)
{
    __shared__ float fv[NT], nfv[NT];
    int tid = threadIdx.x;
    if (tid < NT) fv[tid] = (tid == START) ? 0.f : NEGV;
    __syncwarp();
    for (int b = 0; b < 128; ++b) {
        if (tid < NT) {
            float m = -3.4e38f, v[NT];
            #pragma unroll
            for (int k = 0; k < NT; ++k) { v[k] = g_chunk[b][tid * NT + k] + fv[k]; m = fmaxf(m, v[k]); }
            float s = 0.f;
            #pragma unroll
            for (int k = 0; k < NT; ++k) s += expf(v[k] - m);
            nfv[tid] = m + logf(s);
        }
        __syncwarp();
        if (tid < NT) fv[tid] = nfv[tid];
        __syncwarp();
    }
    if (tid == 0) {
        float m = -3.4e38f, v[NT];
        #pragma unroll
        for (int k = 0; k < NT; ++k) { v[k] = trans[STOP * NT + k] + fv[k]; m = fmaxf(m, v[k]); }
        float s = 0.f;
        #pragma unroll
        for (int k = 0; k < NT; ++k) s += expf(v[k] - m);
        out[0] = m + logf(s);
    }
}

// ---------------- launch ----------------
extern "C" void kernel_launch(void* const* d_in, const int* in_sizes, int n_in,
                              void* d_out, int out_size)
{
    const int*   sentence = (const int*)  d_in[0];
    const float* emb      = (const float*)d_in[1];
    const float* Wihf     = (const float*)d_in[2];
    const float* Whhf     = (const float*)d_in[3];
    const float* bf       = (const float*)d_in[4];
    const float* Wihb     = (const float*)d_in[5];
    const float* Whhb     = (const float*)d_in[6];
    const float* bb       = (const float*)d_in[7];
    const float* Wout     = (const float*)d_in[8];
    const float* bout     = (const float*)d_in[9];
    const float* trans    = (const float*)d_in[10];
    const float* h0       = (const float*)d_in[11];
    const float* c0       = (const float*)d_in[12];

    const size_t smem_bytes = (size_t)(GROWS * H2 + GROWS + RPC) * sizeof(float);
    cudaFuncSetAttribute(lstm_kernel, cudaFuncAttributeMaxDynamicSharedMemorySize, (int)smem_bytes);

    init_kernel<<<L_SEQ + 1, 128>>>(sentence, emb, h0);
    xproj_kernel<<<dim3(L_SEQ / BM, G4 / BN, 2), 256>>>(Wihf, Wihb, bf, bb);
    lstm_kernel<<<2 * NCTA_DIR, 256, smem_bytes>>>(Whhf, Whhb, c0);
    feats_kernel<<<L_SEQ, 384>>>(Wout, bout);
    crf_chunk_kernel<<<128, NT * NT>>>(trans);
    crf_final_kernel<<<1, 32>>>(trans, (float*)d_out);
}

// round 5
// speedup vs baseline: 1.3825x; 1.0445x over previous
#include <cuda_runtime.h>
#include <cuda_bf16.h>
#include <math.h>

// Problem constants
#define L_SEQ 2048
#define E_DIM 512
#define H2    512
#define G4    2048            // 4*H2 gate rows per direction
#define NT    12
#define START 10
#define STOP  11
#define NEGV  -10000.0f

#define NCTA_DIR 64           // CTAs per direction
#define RPC 8                 // hidden units per CTA
#define GROWS 32              // gate rows per CTA

// ---------------- device scratch (no cudaMalloc allowed) ----------------
__device__ float g_xs[L_SEQ * E_DIM];              // embedded sentence, 4 MB
__device__ float g_xw[2 * L_SEQ * G4];             // precomputed input projections (permuted)
__device__ float g_hs[2][(L_SEQ + 1) * H2];        // h history per direction (slot 0 = h0)
__device__ float g_feats[L_SEQ * NT];
__device__ float g_chunk[128][NT * NT];            // CRF chunk matrices
__device__ unsigned g_flag[2][NCTA_DIR];           // per-CTA step-completion flags

// ---------------- init: embedding gather + flags/h0 init ----------------
__global__ void init_kernel(const int* __restrict__ sentence,
                            const float* __restrict__ emb,
                            const float* __restrict__ h0)
{
    int b = blockIdx.x;
    if (b < L_SEQ) {
        int row = sentence[b];
        const float4* src = (const float4*)(emb + (size_t)row * E_DIM);
        float4* dst = (float4*)(g_xs + (size_t)b * E_DIM);
        dst[threadIdx.x] = src[threadIdx.x];   // 128 threads x float4 = 512 floats
    } else {
        if (threadIdx.x < 2 * NCTA_DIR) ((unsigned*)g_flag)[threadIdx.x] = 0;
        const float4* s = (const float4*)h0;
        for (int i = threadIdx.x; i < 2 * (H2 / 4); i += 128) {
            int d = i >> 7;
            int q = i & 127;
            ((float4*)(g_hs[d]))[q] = s[i];
        }
    }
}

// ---------------- input projection GEMM: xw = xs @ Wih^T + b ----------------
// Output permuted so scan-CTA `sub` reads 32 contiguous floats:
//   gate row n (= g*512 + j) -> xw[dir][pos][ (j>>3)*32 + g*8 + (j&7) ]
#define BM 128
#define BN 64
#define BK 16
__global__ void __launch_bounds__(256) xproj_kernel(
    const float* __restrict__ Wf, const float* __restrict__ Wb,
    const float* __restrict__ bfv, const float* __restrict__ bbv)
{
    __shared__ float As[BK][BM + 4];
    __shared__ float Bs[BK][BN + 4];
    const int dir = blockIdx.z;
    const float* W    = dir ? Wb  : Wf;
    const float* bias = dir ? bbv : bfv;
    const int m0 = blockIdx.x * BM;
    const int n0 = blockIdx.y * BN;
    const int tid = threadIdx.x;
    const int tx = tid & 15, ty = tid >> 4;

    float acc[8][4] = {};
    for (int k0 = 0; k0 < E_DIM; k0 += BK) {
        #pragma unroll
        for (int u = 0; u < 2; ++u) {
            int idx = tid + u * 256;
            int r = idx >> 2, q = idx & 3;
            float4 v = *(const float4*)(g_xs + (size_t)(m0 + r) * E_DIM + k0 + q * 4);
            As[q*4+0][r] = v.x; As[q*4+1][r] = v.y; As[q*4+2][r] = v.z; As[q*4+3][r] = v.w;
        }
        {
            int r = tid >> 2, q = tid & 3;
            float4 v = *(const float4*)(W + (size_t)(n0 + r) * E_DIM + k0 + q * 4);
            Bs[q*4+0][r] = v.x; Bs[q*4+1][r] = v.y; Bs[q*4+2][r] = v.z; Bs[q*4+3][r] = v.w;
        }
        __syncthreads();
        #pragma unroll
        for (int kk = 0; kk < BK; ++kk) {
            float a[8], b[4];
            #pragma unroll
            for (int i = 0; i < 8; ++i) a[i] = As[kk][ty * 8 + i];
            #pragma unroll
            for (int j = 0; j < 4; ++j) b[j] = Bs[kk][tx * 4 + j];
            #pragma unroll
            for (int i = 0; i < 8; ++i)
                #pragma unroll
                for (int j = 0; j < 4; ++j) acc[i][j] += a[i] * b[j];
        }
        __syncthreads();
    }
    // epilogue: add bias, permuted store (4 output cols stay contiguous)
    const int nb = n0 + tx * 4;          // 4-aligned gate row
    const int g  = nb >> 9, jj = nb & 511;
    const int sub = jj >> 3, slot = g * 8 + (jj & 7);   // slot 4-aligned
    float b0 = bias[nb], b1 = bias[nb+1], b2 = bias[nb+2], b3 = bias[nb+3];
    #pragma unroll
    for (int i = 0; i < 8; ++i) {
        int m = m0 + ty * 8 + i;
        float4 o;
        o.x = acc[i][0] + b0; o.y = acc[i][1] + b1;
        o.z = acc[i][2] + b2; o.w = acc[i][3] + b3;
        *(float4*)(g_xw + ((size_t)(dir * L_SEQ + m)) * G4 + sub * 32 + slot) = o;
    }
}

// ---------------- persistent bidirectional LSTM scan (Whh only) ----------------
__global__ void __launch_bounds__(256, 1) lstm_kernel(
    const float* __restrict__ Whhf, const float* __restrict__ Whhb,
    const float* __restrict__ c0)
{
    extern __shared__ float sm[];
    float* Whh_s = sm;                 // 32*512 = 16384 floats (64 KB)
    float* gsum  = sm + GROWS * H2;    // 32
    float* c_s   = gsum + GROWS;       // 8

    const int dir = blockIdx.x / NCTA_DIR;
    const int sub = blockIdx.x % NCTA_DIR;
    const int k0  = sub * RPC;
    const float* Whh = dir ? Whhb : Whhf;
    const int tid = threadIdx.x;

    // load this CTA's 32 Whh gate rows into SMEM
    for (int i = tid; i < GROWS * (H2 / 4); i += 256) {
        int lr = i >> 7, c4 = i & 127;
        int g = lr >> 3, k = lr & 7;
        ((float4*)Whh_s)[i] = ((const float4*)(Whh + (size_t)(g * H2 + k0 + k) * H2))[c4];
    }
    if (tid < RPC) c_s[tid] = c0[dir * H2 + k0 + tid];
    __syncthreads();

    float* hist = g_hs[dir];
    const float* xw_base = g_xw + (size_t)dir * L_SEQ * G4 + sub * 32;
    unsigned* flags = g_flag[dir];
    const int w = tid >> 5, l = tid & 31;

    for (int t = 0; t < L_SEQ; ++t) {
        const int pos = dir ? (L_SEQ - 1 - t) : t;

        // prefetch this warp's 4 xw values (lane 0) — recurrence-independent
        float xr[4];
        if (l == 0) {
            const float* xp = xw_base + (size_t)pos * G4;
            #pragma unroll
            for (int r = 0; r < 4; ++r) xr[r] = __ldcg(xp + w * 4 + r);
        }

        // wait for all 64 producer flags of this direction to reach t (wrap-proof compare)
        if (tid < NCTA_DIR) {
            unsigned v;
            do {
                asm volatile("ld.acquire.gpu.u32 %0, [%1];" : "=r"(v) : "l"(flags + tid));
            } while ((int)(v - (unsigned)t) < 0);
        }
        __syncthreads();

        // load h_t directly to registers (ordered by the acquire + barrier)
        const float4* hv = (const float4*)(hist + (size_t)t * H2);
        float4 h4[4];
        #pragma unroll
        for (int j = 0; j < 4; ++j) h4[j] = __ldcg(hv + l + 32 * j);

        // GEMV: warp w computes gate rows 4w..4w+3
        #pragma unroll
        for (int r = 0; r < 4; ++r) {
            const int lr = w * 4 + r;
            const float4* wr = (const float4*)(Whh_s + lr * H2);
            float acc = 0.f;
            #pragma unroll
            for (int j = 0; j < 4; ++j) {
                float4 ww = wr[l + 32 * j];
                acc += ww.x * h4[j].x + ww.y * h4[j].y + ww.z * h4[j].z + ww.w * h4[j].w;
            }
            #pragma unroll
            for (int off = 16; off; off >>= 1) acc += __shfl_xor_sync(0xffffffffu, acc, off);
            if (l == 0) gsum[lr] = acc + xr[r];
        }
        __syncthreads();

        // gate update + publish (warp 0 only; other warps race ahead to next poll)
        if (tid < 32) {
            if (tid < RPC) {
                float ig = 1.f / (1.f + expf(-gsum[tid]));
                float fg = 1.f / (1.f + expf(-gsum[8 + tid]));
                float gg = tanhf(gsum[16 + tid]);
                float og = 1.f / (1.f + expf(-gsum[24 + tid]));
                float c = fg * c_s[tid] + ig * gg;
                c_s[tid] = c;
                float hn = og * tanhf(c);
                __stcg(hist + (size_t)(t + 1) * H2 + k0 + tid, hn);
            }
            __syncwarp();
            if (tid == 0)
                asm volatile("st.release.gpu.u32 [%0], %1;"
                             :: "l"(flags + sub), "r"((unsigned)(t + 1)) : "memory");
        }
    }
}

// ---------------- output projection: feats[t][i] ----------------
__global__ void feats_kernel(const float* __restrict__ W_out, const float* __restrict__ b_out)
{
    int t = blockIdx.x;
    int w = threadIdx.x >> 5, l = threadIdx.x & 31;  // 12 warps
    const float* hf = g_hs[0] + (size_t)(t + 1) * H2;
    const float* hb = g_hs[1] + (size_t)(L_SEQ - t) * H2;
    const float* wo = W_out + (size_t)w * (2 * H2);
    float acc = 0.f;
    for (int c = l; c < H2; c += 32)
        acc += hf[c] * wo[c] + hb[c] * wo[H2 + c];
    #pragma unroll
    for (int off = 16; off; off >>= 1) acc += __shfl_xor_sync(0xffffffffu, acc, off);
    if (l == 0) g_feats[t * NT + w] = acc + b_out[w];
}

// ---------------- CRF: chunked log-semiring scan ----------------
__global__ void crf_chunk_kernel(const float* __restrict__ trans)
{
    __shared__ float tr[NT * NT], cur[NT * NT];
    int tid = threadIdx.x;           // 0..143
    int i = tid / NT, j = tid % NT;
    tr[tid] = trans[tid];
    int t0 = blockIdx.x * 16;
    cur[tid] = trans[tid] + g_feats[t0 * NT + i];
    __syncthreads();
    for (int s = 1; s < 16; ++s) {
        float ft = g_feats[(t0 + s) * NT + i];
        float v[NT];
        float m = -3.4e38f;
        #pragma unroll
        for (int k = 0; k < NT; ++k) { v[k] = tr[i * NT + k] + cur[k * NT + j]; m = fmaxf(m, v[k]); }
        float ssum = 0.f;
        #pragma unroll
        for (int k = 0; k < NT; ++k) ssum += expf(v[k] - m);
        float r = ft + m + logf(ssum);
        __syncthreads();
        cur[tid] = r;
        __syncthreads();
    }
    g_chunk[blockIdx.x][tid] = cur[tid];
}

__global__ void crf_final_kernel(const float* __restrict__ trans, float* __restrict__ out)
{
    __shared__ float fv[NT], nfv[NT];
    int tid = threadIdx.x;
    if (tid < NT) fv[tid] = (tid == START) ? 0.f : NEGV;
    __syncwarp();
    for (int b = 0; b < 128; ++b) {
        if (tid < NT) {
            float m = -3.4e38f, v[NT];
            #pragma unroll
            for (int k = 0; k < NT; ++k) { v[k] = g_chunk[b][tid * NT + k] + fv[k]; m = fmaxf(m, v[k]); }
            float s = 0.f;
            #pragma unroll
            for (int k = 0; k < NT; ++k) s += expf(v[k] - m);
            nfv[tid] = m + logf(s);
        }
        __syncwarp();
        if (tid < NT) fv[tid] = nfv[tid];
        __syncwarp();
    }
    if (tid == 0) {
        float m = -3.4e38f, v[NT];
        #pragma unroll
        for (int k = 0; k < NT; ++k) { v[k] = trans[STOP * NT + k] + fv[k]; m = fmaxf(m, v[k]); }
        float s = 0.f;
        #pragma unroll
        for (int k = 0; k < NT; ++k) s += expf(v[k] - m);
        out[0] = m + logf(s);
    }
}

// ---------------- launch ----------------
extern "C" void kernel_launch(void* const* d_in, const int* in_sizes, int n_in,
                              void* d_out, int out_size)
{
    const int*   sentence = (const int*)  d_in[0];
    const float* emb      = (const float*)d_in[1];
    const float* Wihf     = (const float*)d_in[2];
    const float* Whhf     = (const float*)d_in[3];
    const float* bf       = (const float*)d_in[4];
    const float* Wihb     = (const float*)d_in[5];
    const float* Whhb     = (const float*)d_in[6];
    const float* bb       = (const float*)d_in[7];
    const float* Wout     = (const float*)d_in[8];
    const float* bout     = (const float*)d_in[9];
    const float* trans    = (const float*)d_in[10];
    const float* h0       = (const float*)d_in[11];
    const float* c0       = (const float*)d_in[12];

    const size_t smem_bytes = (size_t)(GROWS * H2 + GROWS + RPC) * sizeof(float);
    cudaFuncSetAttribute(lstm_kernel, cudaFuncAttributeMaxDynamicSharedMemorySize, (int)smem_bytes);

    init_kernel<<<L_SEQ + 1, 128>>>(sentence, emb, h0);
    xproj_kernel<<<dim3(L_SEQ / BM, G4 / BN, 2), 256>>>(Wihf, Wihb, bf, bb);
    lstm_kernel<<<2 * NCTA_DIR, 256, smem_bytes>>>(Whhf, Whhb, c0);
    feats_kernel<<<L_SEQ, 384>>>(Wout, bout);
    crf_chunk_kernel<<<128, NT * NT>>>(trans);
    crf_final_kernel<<<1, 32>>>(trans, (float*)d_out);
}